// round 7
// baseline (speedup 1.0000x reference)
#include <cuda_runtime.h>
#include <cuda_fp16.h>
#include <mma.h>
#include <math.h>

using namespace nvcuda;

#define TT 2048
#define DD 1024
#define NH 8
#define HD 128
#define GATE_IN 12

#define ATTN_SCALE 0.12f
#define RMS_EPS 1e-6f
#define LOG2E 1.4426950408889634f
#define SOFT_SHIFT 8.0f

static __device__ float g_qkv[(size_t)TT * 3 * DD];   // [t][3*D]
static __device__ float g_qh[(size_t)NH * TT * HD];   // [h][t][hd]  scaled hi
static __device__ float g_ql[(size_t)NH * TT * HD];   // scaled lo
static __device__ float g_kh[(size_t)NH * TT * HD];
static __device__ float g_kl[(size_t)NH * TT * HD];
static __device__ float g_v[(size_t)NH * TT * HD];
static __device__ float g_y[(size_t)TT * DD];         // [t][h*HD+hd]

// truncate a float to tf32 precision (drop low 13 mantissa bits). No asm.
__device__ __forceinline__ float tf32_hi(float v) {
    return __uint_as_float(__float_as_uint(v) & 0xFFFFE000u);
}

// ---------------------------------------------------------------------------
// Split-tf32 GEMM via wmma: C[m][n] = sum_k A[m][k] * W[n][k]
// Block 128x128, BK=16, 256 threads = 8 warps in 2x4 grid; warp tile 64x32.
// hi/lo split done ONCE per tile at smem store time; inner loop is pure
// fragment loads + mma. Register-prefetch double buffering.
// MODE 0: A = external (x), C = g_qkv.  MODE 1: A = g_y, C = external.
// ---------------------------------------------------------------------------
template <int MODE>
__global__ void __launch_bounds__(256, 2) gemm_wmma_kernel(
    const float* __restrict__ Aext, const float* __restrict__ Bw,
    float* __restrict__ Cext, int M, int N, int K)
{
    const float* __restrict__ A = (MODE == 0) ? Aext : (const float*)g_y;
    float* __restrict__ C       = (MODE == 0) ? (float*)g_qkv : Cext;

    __shared__ float Ah[128][20];   // [m][k] hi
    __shared__ float Al[128][20];   // [m][k] lo
    __shared__ float Bh[128][20];   // [n][k] hi
    __shared__ float Bl[128][20];   // [n][k] lo

    const int tid = threadIdx.x;
    const int warp = tid >> 5;
    const int wm = warp >> 2;       // 0..1
    const int wn = warp & 3;        // 0..3
    const int bm = blockIdx.y * 128, bn = blockIdx.x * 128;
    const int lrow = tid >> 2;          // 0..63
    const int lc4 = (tid & 3) * 4;      // 0,4,8,12

    wmma::fragment<wmma::accumulator, 16, 16, 8, float> acc[4][2];
#pragma unroll
    for (int mt = 0; mt < 4; mt++)
#pragma unroll
        for (int nt = 0; nt < 2; nt++)
            wmma::fill_fragment(acc[mt][nt], 0.0f);

    // preload tile 0 into registers
    float4 ar[2], br[2];
#pragma unroll
    for (int p = 0; p < 2; p++) {
        const int rr = lrow + p * 64;
        ar[p] = *(const float4*)(A + (size_t)(bm + rr) * K + lc4);
        br[p] = *(const float4*)(Bw + (size_t)(bn + rr) * K + lc4);
    }

    for (int kt = 0; kt < K; kt += 16) {
        // split current registers into smem (hi/lo), once per tile
#pragma unroll
        for (int p = 0; p < 2; p++) {
            const int rr = lrow + p * 64;
            float va[4];
            va[0] = ar[p].x; va[1] = ar[p].y; va[2] = ar[p].z; va[3] = ar[p].w;
#pragma unroll
            for (int j = 0; j < 4; j++) {
                float hi = tf32_hi(va[j]);
                Ah[rr][lc4 + j] = hi;
                Al[rr][lc4 + j] = tf32_hi(va[j] - hi);
            }
            float vb[4];
            vb[0] = br[p].x; vb[1] = br[p].y; vb[2] = br[p].z; vb[3] = br[p].w;
#pragma unroll
            for (int j = 0; j < 4; j++) {
                float hi = tf32_hi(vb[j]);
                Bh[rr][lc4 + j] = hi;
                Bl[rr][lc4 + j] = tf32_hi(vb[j] - hi);
            }
        }
        __syncthreads();

        // prefetch next tile into registers (overlaps with compute below)
        if (kt + 16 < K) {
#pragma unroll
            for (int p = 0; p < 2; p++) {
                const int rr = lrow + p * 64;
                ar[p] = *(const float4*)(A + (size_t)(bm + rr) * K + kt + 16 + lc4);
                br[p] = *(const float4*)(Bw + (size_t)(bn + rr) * K + kt + 16 + lc4);
            }
        }

        // compute: pure fragment loads + mma
#pragma unroll
        for (int ks = 0; ks < 16; ks += 8) {
            wmma::fragment<wmma::matrix_a, 16, 16, 8,
                           wmma::precision::tf32, wmma::row_major> fah[4], fal[4];
#pragma unroll
            for (int mt = 0; mt < 4; mt++) {
                wmma::load_matrix_sync(fah[mt], &Ah[wm * 64 + mt * 16][ks], 20);
                wmma::load_matrix_sync(fal[mt], &Al[wm * 64 + mt * 16][ks], 20);
            }
            wmma::fragment<wmma::matrix_b, 16, 16, 8,
                           wmma::precision::tf32, wmma::col_major> fbh[2], fbl[2];
#pragma unroll
            for (int nt = 0; nt < 2; nt++) {
                wmma::load_matrix_sync(fbh[nt], &Bh[wn * 32 + nt * 16][ks], 20);
                wmma::load_matrix_sync(fbl[nt], &Bl[wn * 32 + nt * 16][ks], 20);
            }
#pragma unroll
            for (int mt = 0; mt < 4; mt++)
#pragma unroll
                for (int nt = 0; nt < 2; nt++) {
                    wmma::mma_sync(acc[mt][nt], fah[mt], fbh[nt], acc[mt][nt]);
                    wmma::mma_sync(acc[mt][nt], fal[mt], fbh[nt], acc[mt][nt]);
                    wmma::mma_sync(acc[mt][nt], fah[mt], fbl[nt], acc[mt][nt]);
                }
        }
        __syncthreads();
    }

#pragma unroll
    for (int mt = 0; mt < 4; mt++)
#pragma unroll
        for (int nt = 0; nt < 2; nt++) {
            float* cp = C + (size_t)(bm + wm * 64 + mt * 16) * N
                          + bn + wn * 32 + nt * 16;
            wmma::store_matrix_sync(cp, acc[mt][nt], N, wmma::mem_row_major);
        }
}

// ---------------------------------------------------------------------------
// Postprocess: per (t,h): rms_norm + rotary on q,k; v = l0*v + l1*ve.
// Writes pre-scaled, pre-split tf32 hi/lo for q and k.
// ---------------------------------------------------------------------------
__global__ void postproc_kernel(const float* __restrict__ ve,
                                const float* __restrict__ lam,
                                const float* __restrict__ cosb,
                                const float* __restrict__ sinb)
{
    const int t = blockIdx.x >> 3;
    const int h = blockIdx.x & 7;
    const int hd = threadIdx.x;

    const float* rowp = g_qkv + (size_t)t * (3 * DD) + h * HD;
    float qv = rowp[hd];
    float kv = rowp[DD + hd];
    float vv = rowp[2 * DD + hd];

    float sq = qv * qv, sk = kv * kv;
#pragma unroll
    for (int o = 16; o; o >>= 1) {
        sq += __shfl_xor_sync(0xffffffffu, sq, o);
        sk += __shfl_xor_sync(0xffffffffu, sk, o);
    }
    __shared__ float red[2][4];
    int w = hd >> 5, lane = hd & 31;
    if (lane == 0) { red[0][w] = sq; red[1][w] = sk; }
    __syncthreads();
    sq = red[0][0] + red[0][1] + red[0][2] + red[0][3];
    sk = red[1][0] + red[1][1] + red[1][2] + red[1][3];
    float qr = rsqrtf(sq * (1.0f / HD) + RMS_EPS);
    float kr = rsqrtf(sk * (1.0f / HD) + RMS_EPS);

    __shared__ float qn[HD], kn[HD];
    qn[hd] = qv * qr;
    kn[hd] = kv * kr;
    __syncthreads();

    float qo, ko;
    if (hd < 64) {
        float cc = cosb[t * 64 + hd];
        float ss = sinb[t * 64 + hd];
        qo = qn[hd] * cc + qn[hd + 64] * ss;
        ko = kn[hd] * cc + kn[hd + 64] * ss;
    } else {
        int j = hd - 64;
        float cc = cosb[t * 64 + j];
        float ss = sinb[t * 64 + j];
        qo = -qn[j] * ss + qn[hd] * cc;
        ko = -kn[j] * ss + kn[hd] * cc;
    }
    const float lm0 = __ldg(lam);
    const float lm1 = __ldg(lam + 1);
    size_t oidx = ((size_t)h * TT + t) * HD + hd;

    float qs = qo * (ATTN_SCALE * LOG2E);
    float qhv = tf32_hi(qs);
    g_qh[oidx] = qhv;
    g_ql[oidx] = tf32_hi(qs - qhv);
    float khv = tf32_hi(ko);
    g_kh[oidx] = khv;
    g_kl[oidx] = tf32_hi(ko - khv);
    g_v[oidx] = lm0 * vv + lm1 * ve[((size_t)t * NH + h) * HD + hd];
}

// ---------------------------------------------------------------------------
// Flash attention via wmma. Grid (32, 8), 128 threads = 4 warps.
// Block q-tile 64 rows; warp owns 16 rows. Key tiles of 32.
// QK: 3-term tf32 using pre-split q/k (qh persistent in regs; ql, kl
// fragments loaded from global/L1; kh staged in smem).
// Softmax: fixed shift exp2(s - 8); O never rescaled.
// PV: half wmma; normalize + gate in epilogue.
// ---------------------------------------------------------------------------
__global__ void __launch_bounds__(128) flash_wmma_kernel(
    const float* __restrict__ x, const float* __restrict__ gate_w)
{
    // smem layout (bytes):
    //   0     : Khs  32 x 132 f32  = 16896
    //   16896 : Vsm  32 x 136 half =  8704
    //   25600 : Ssm  per warp 16 x 36 f32 (2304 each, 4 warps) = 9216
    //   34816 : Psm  per warp 16 x 40 half (1280 each, 4 warps) = 5120
    //   total : 39936.  Epilogue reuses offset 0 as per-warp 16 x 132 f32.
    __shared__ __align__(16) unsigned char smraw[39936];
    float  (*Khs)[132] = (float  (*)[132])(smraw);
    __half (*Vsm)[136] = (__half (*)[136])(smraw + 16896);

    const int h = blockIdx.y;
    const int qb = (int)gridDim.x - 1 - (int)blockIdx.x;   // heavy tiles first
    const int tid = threadIdx.x, warp = tid >> 5, lane = tid & 31;
    const int qbase = qb * 64;
    const int wrow0 = qbase + warp * 16;
    const int myrow = lane >> 1;
    const int myhalf = lane & 1;
    const int grow = wrow0 + myrow;

    float  (*Ssm_w)[36] = (float  (*)[36])(smraw + 25600 + warp * 2304);
    __half (*Psm_w)[40] = (__half (*)[40])(smraw + 34816 + warp * 1280);

    const float* Qhp = g_qh + (size_t)h * TT * HD;
    const float* Qlp = g_ql + (size_t)h * TT * HD;
    const float* Khp = g_kh + (size_t)h * TT * HD;
    const float* Klp = g_kl + (size_t)h * TT * HD;
    const float* Vp  = g_v  + (size_t)h * TT * HD;

    // persistent qh fragments (already scaled + tf32-truncated)
    wmma::fragment<wmma::matrix_a, 16, 16, 8,
                   wmma::precision::tf32, wmma::row_major> qhf[16];
#pragma unroll
    for (int kt = 0; kt < 16; kt++)
        wmma::load_matrix_sync(qhf[kt], Qhp + (size_t)wrow0 * HD + kt * 8, HD);

    wmma::fragment<wmma::accumulator, 16, 16, 16, float> oacc[8];
#pragma unroll
    for (int nt = 0; nt < 8; nt++) wmma::fill_fragment(oacc[nt], 0.0f);
    float lrun = 0.0f;

    const int nkb = 2 * qb + 2;
    for (int kb = 0; kb < nkb; kb++) {
        const int kbase = kb * 32;
        __syncthreads();
        // cooperative load: Kh tile f32 -> smem, V tile -> half smem
#pragma unroll
        for (int i = 0; i < 8; i++) {
            int idx = tid + i * 128;
            int rr = idx >> 5;
            int c4 = (idx & 31) * 4;
            *(float4*)&Khs[rr][c4] =
                *(const float4*)(Khp + (size_t)(kbase + rr) * HD + c4);
            float4 vv4 = *(const float4*)(Vp + (size_t)(kbase + rr) * HD + c4);
            *(__half2*)&Vsm[rr][c4]     = __floats2half2_rn(vv4.x, vv4.y);
            *(__half2*)&Vsm[rr][c4 + 2] = __floats2half2_rn(vv4.z, vv4.w);
        }
        __syncthreads();

        const bool active = (kbase <= wrow0 + 15);   // warp-uniform
        if (active) {
            wmma::fragment<wmma::accumulator, 16, 16, 8, float> sacc[2];
            wmma::fill_fragment(sacc[0], 0.0f);
            wmma::fill_fragment(sacc[1], 0.0f);
#pragma unroll
            for (int kt = 0; kt < 16; kt++) {
                wmma::fragment<wmma::matrix_a, 16, 16, 8,
                               wmma::precision::tf32, wmma::row_major> qlf;
                wmma::load_matrix_sync(qlf, Qlp + (size_t)wrow0 * HD + kt * 8, HD);
#pragma unroll
                for (int nt = 0; nt < 2; nt++) {
                    wmma::fragment<wmma::matrix_b, 16, 16, 8,
                                   wmma::precision::tf32, wmma::col_major> khf, klf;
                    wmma::load_matrix_sync(khf, &Khs[nt * 16][kt * 8], 132);
                    wmma::load_matrix_sync(klf,
                        Klp + (size_t)(kbase + nt * 16) * HD + kt * 8, HD);
                    wmma::mma_sync(sacc[nt], qhf[kt], khf, sacc[nt]);
                    wmma::mma_sync(sacc[nt], qhf[kt], klf, sacc[nt]);
                    wmma::mma_sync(sacc[nt], qlf,     khf, sacc[nt]);
                }
            }
            wmma::store_matrix_sync(&Ssm_w[0][0],  sacc[0], 36, wmma::mem_row_major);
            wmma::store_matrix_sync(&Ssm_w[0][16], sacc[1], 36, wmma::mem_row_major);
        }
        __syncwarp();
        if (active) {
            // softmax with fixed shift; causal mask; write P as half
            float lsum = 0.0f;
#pragma unroll
            for (int j = 0; j < 16; j++) {
                int col = myhalf * 16 + j;
                int gcol = kbase + col;
                float sv = Ssm_w[myrow][col];
                float p = (gcol <= grow) ? exp2f(sv - SOFT_SHIFT) : 0.0f;
                lsum += p;
                Psm_w[myrow][col] = __float2half(p);
            }
            lsum += __shfl_xor_sync(0xffffffffu, lsum, 1);
            lrun += lsum;
        }
        __syncwarp();
        if (active) {
            // O += P V  (half wmma)
#pragma unroll
            for (int ks = 0; ks < 2; ks++) {
                wmma::fragment<wmma::matrix_a, 16, 16, 16,
                               __half, wmma::row_major> pfrag;
                wmma::load_matrix_sync(pfrag, &Psm_w[0][ks * 16], 40);
#pragma unroll
                for (int nt = 0; nt < 8; nt++) {
                    wmma::fragment<wmma::matrix_b, 16, 16, 16,
                                   __half, wmma::row_major> vfrag;
                    wmma::load_matrix_sync(vfrag, &Vsm[ks * 16][nt * 16], 136);
                    wmma::mma_sync(oacc[nt], pfrag, vfrag, oacc[nt]);
                }
            }
        }
    }

    // epilogue: stage O to smem, normalize, gate, store
    __syncthreads();
    float (*Osm_w)[132] = (float (*)[132])(smraw + warp * 8448);
#pragma unroll
    for (int nt = 0; nt < 8; nt++)
        wmma::store_matrix_sync(&Osm_w[0][nt * 16], oacc[nt], 132,
                                wmma::mem_row_major);
    __syncwarp();

    float gd = 0.0f;
#pragma unroll
    for (int i = 0; i < GATE_IN; i++)
        gd += x[(size_t)grow * DD + i] * gate_w[h * GATE_IN + i];
    float gate = 1.0f / (1.0f + expf(-gd));
    float scale = gate / lrun;

    const int c0 = myhalf * 64;
    float* yrow = g_y + (size_t)grow * DD + h * HD;
#pragma unroll
    for (int j = 0; j < 16; j++) {
        float4 ov = *(float4*)&Osm_w[myrow][c0 + j * 4];
        ov.x *= scale; ov.y *= scale; ov.z *= scale; ov.w *= scale;
        *(float4*)(yrow + c0 + j * 4) = ov;
    }
}

// ---------------------------------------------------------------------------
extern "C" void kernel_launch(void* const* d_in, const int* in_sizes, int n_in,
                              void* d_out, int out_size)
{
    const float* x      = (const float*)d_in[0];  // (1,2048,1024)
    const float* qkvo_w = (const float*)d_in[1];  // (4,1024,1024)
    const float* gate_w = (const float*)d_in[2];  // (8,12)
    const float* ve     = (const float*)d_in[3];  // (1,2048,8,128)
    const float* lam    = (const float*)d_in[4];  // (2,)
    const float* cosb   = (const float*)d_in[5];  // (2048,64)
    const float* sinb   = (const float*)d_in[6];  // (2048,64)
    float* out = (float*)d_out;                   // (1,2048,1024)

    // 1) QKV projection -> g_qkv
    {
        dim3 grid(3072 / 128, 2048 / 128);
        gemm_wmma_kernel<0><<<grid, 256>>>(x, qkvo_w, nullptr, TT, 3 * DD, DD);
    }
    // 2) rms_norm + rotary + value mix + split
    postproc_kernel<<<TT * NH, 128>>>(ve, lam, cosb, sinb);
    // 3) causal flash attention + gate -> g_y
    {
        dim3 grid(TT / 64, NH);
        flash_wmma_kernel<<<grid, 128>>>(x, gate_w);
    }
    // 4) output projection
    {
        dim3 grid(1024 / 128, 2048 / 128);
        gemm_wmma_kernel<1><<<grid, 256>>>(nullptr, qkvo_w + (size_t)3 * DD * DD,
                                           out, TT, DD, DD);
    }
}

// round 8
// speedup vs baseline: 2.1771x; 2.1771x over previous
#include <cuda_runtime.h>
#include <cuda_fp16.h>
#include <mma.h>
#include <math.h>

using namespace nvcuda;

#define TT 2048
#define DD 1024
#define NH 8
#define HD 128
#define GATE_IN 12

#define ATTN_SCALE 0.12f
#define RMS_EPS 1e-6f
#define LOG2E 1.4426950408889634f
#define SOFT_SHIFT 8.0f

static __device__ float g_qkv[(size_t)TT * 3 * DD];   // [t][3*D]
static __device__ float g_q[(size_t)NH * TT * HD];    // [h][t][hd]
static __device__ float g_k[(size_t)NH * TT * HD];
static __device__ float g_v[(size_t)NH * TT * HD];
static __device__ float g_y[(size_t)TT * DD];         // [t][h*HD+hd]

// truncate a float to tf32 precision (drop low 13 mantissa bits). No asm.
__device__ __forceinline__ float tf32_hi(float v) {
    return __uint_as_float(__float_as_uint(v) & 0xFFFFE000u);
}

// ---------------------------------------------------------------------------
// Split-f16 GEMM via wmma: C[m][n] = sum_k A[m][k] * W[n][k]
// Block 128x128, BK=16, 256 threads = 8 warps (2x4 grid); warp tile 64x32.
// Each input x = h + l with h,l f16 (22-bit effective mantissa);
// D = ah*bh + al*bh + ah*bl  (f32 accumulate; dropped al*bl ~ 2^-22).
// Split done once at smem store; inner loop pure fragment loads + mma.
// MODE 0: A = external (x), C = g_qkv.  MODE 1: A = g_y, C = external.
// ---------------------------------------------------------------------------
template <int MODE>
__global__ void __launch_bounds__(256) gemm_f16x3_kernel(
    const float* __restrict__ Aext, const float* __restrict__ Bw,
    float* __restrict__ Cext, int M, int N, int K)
{
    const float* __restrict__ A = (MODE == 0) ? Aext : (const float*)g_y;
    float* __restrict__ C       = (MODE == 0) ? (float*)g_qkv : Cext;

    __shared__ __half Ah[128][24];   // [m][k] hi, ld padded to 24
    __shared__ __half Al[128][24];   // [m][k] lo
    __shared__ __half Bh[128][24];   // [n][k] hi
    __shared__ __half Bl[128][24];   // [n][k] lo

    const int tid = threadIdx.x;
    const int warp = tid >> 5;
    const int wm = warp >> 2;       // 0..1
    const int wn = warp & 3;        // 0..3
    const int bm = blockIdx.y * 128, bn = blockIdx.x * 128;
    const int lrow = tid >> 2;          // 0..63
    const int lc4 = (tid & 3) * 4;      // 0,4,8,12

    wmma::fragment<wmma::accumulator, 16, 16, 16, float> acc[4][2];
#pragma unroll
    for (int mt = 0; mt < 4; mt++)
#pragma unroll
        for (int nt = 0; nt < 2; nt++)
            wmma::fill_fragment(acc[mt][nt], 0.0f);

    for (int kt = 0; kt < K; kt += 16) {
        __syncthreads();
#pragma unroll
        for (int p = 0; p < 2; p++) {
            const int rr = lrow + p * 64;
            float4 av = *(const float4*)(A + (size_t)(bm + rr) * K + kt + lc4);
            float va[4];
            va[0] = av.x; va[1] = av.y; va[2] = av.z; va[3] = av.w;
#pragma unroll
            for (int j = 0; j < 4; j++) {
                __half hv = __float2half_rn(va[j]);
                Ah[rr][lc4 + j] = hv;
                Al[rr][lc4 + j] = __float2half_rn(va[j] - __half2float(hv));
            }
            float4 bv = *(const float4*)(Bw + (size_t)(bn + rr) * K + kt + lc4);
            float vb[4];
            vb[0] = bv.x; vb[1] = bv.y; vb[2] = bv.z; vb[3] = bv.w;
#pragma unroll
            for (int j = 0; j < 4; j++) {
                __half hv = __float2half_rn(vb[j]);
                Bh[rr][lc4 + j] = hv;
                Bl[rr][lc4 + j] = __float2half_rn(vb[j] - __half2float(hv));
            }
        }
        __syncthreads();

        // one k=16 step: pure fragment loads + mma
        wmma::fragment<wmma::matrix_a, 16, 16, 16, __half,
                       wmma::row_major> fah[4], fal[4];
#pragma unroll
        for (int mt = 0; mt < 4; mt++) {
            wmma::load_matrix_sync(fah[mt], &Ah[wm * 64 + mt * 16][0], 24);
            wmma::load_matrix_sync(fal[mt], &Al[wm * 64 + mt * 16][0], 24);
        }
#pragma unroll
        for (int nt = 0; nt < 2; nt++) {
            wmma::fragment<wmma::matrix_b, 16, 16, 16, __half,
                           wmma::col_major> fbh, fbl;
            wmma::load_matrix_sync(fbh, &Bh[wn * 32 + nt * 16][0], 24);
            wmma::load_matrix_sync(fbl, &Bl[wn * 32 + nt * 16][0], 24);
#pragma unroll
            for (int mt = 0; mt < 4; mt++) {
                wmma::mma_sync(acc[mt][nt], fah[mt], fbh, acc[mt][nt]);
                wmma::mma_sync(acc[mt][nt], fal[mt], fbh, acc[mt][nt]);
                wmma::mma_sync(acc[mt][nt], fah[mt], fbl, acc[mt][nt]);
            }
        }
    }

#pragma unroll
    for (int mt = 0; mt < 4; mt++)
#pragma unroll
        for (int nt = 0; nt < 2; nt++) {
            float* cp = C + (size_t)(bm + wm * 64 + mt * 16) * N
                          + bn + wn * 32 + nt * 16;
            wmma::store_matrix_sync(cp, acc[mt][nt], N, wmma::mem_row_major);
        }
}

// ---------------------------------------------------------------------------
// Postprocess: per (t,h): rms_norm + rotary on q,k; v = l0*v + l1*ve.
// ---------------------------------------------------------------------------
__global__ void postproc_kernel(const float* __restrict__ ve,
                                const float* __restrict__ lam,
                                const float* __restrict__ cosb,
                                const float* __restrict__ sinb)
{
    const int t = blockIdx.x >> 3;
    const int h = blockIdx.x & 7;
    const int hd = threadIdx.x;

    const float* rowp = g_qkv + (size_t)t * (3 * DD) + h * HD;
    float qv = rowp[hd];
    float kv = rowp[DD + hd];
    float vv = rowp[2 * DD + hd];

    float sq = qv * qv, sk = kv * kv;
#pragma unroll
    for (int o = 16; o; o >>= 1) {
        sq += __shfl_xor_sync(0xffffffffu, sq, o);
        sk += __shfl_xor_sync(0xffffffffu, sk, o);
    }
    __shared__ float red[2][4];
    int w = hd >> 5, lane = hd & 31;
    if (lane == 0) { red[0][w] = sq; red[1][w] = sk; }
    __syncthreads();
    sq = red[0][0] + red[0][1] + red[0][2] + red[0][3];
    sk = red[1][0] + red[1][1] + red[1][2] + red[1][3];
    float qr = rsqrtf(sq * (1.0f / HD) + RMS_EPS);
    float kr = rsqrtf(sk * (1.0f / HD) + RMS_EPS);

    __shared__ float qn[HD], kn[HD];
    qn[hd] = qv * qr;
    kn[hd] = kv * kr;
    __syncthreads();

    float qo, ko;
    if (hd < 64) {
        float cc = cosb[t * 64 + hd];
        float ss = sinb[t * 64 + hd];
        qo = qn[hd] * cc + qn[hd + 64] * ss;
        ko = kn[hd] * cc + kn[hd + 64] * ss;
    } else {
        int j = hd - 64;
        float cc = cosb[t * 64 + j];
        float ss = sinb[t * 64 + j];
        qo = -qn[j] * ss + qn[hd] * cc;
        ko = -kn[j] * ss + kn[hd] * cc;
    }
    const float lm0 = __ldg(lam);
    const float lm1 = __ldg(lam + 1);
    size_t oidx = ((size_t)h * TT + t) * HD + hd;
    g_q[oidx] = qo;
    g_k[oidx] = ko;
    g_v[oidx] = lm0 * vv + lm1 * ve[((size_t)t * NH + h) * HD + hd];
}

// ---------------------------------------------------------------------------
// Flash attention via wmma (identical to the measured-good round-6 version).
// Grid (32, 8), 128 threads = 4 warps; warp owns 16 q rows; key tiles of 32.
// QK: tf32 wmma with 3-term split (scale and log2e folded into Q).
// Softmax: fixed shift exp2(s - 8); O accumulators never rescaled.
// PV: half wmma; normalize + gate in epilogue via smem staging.
// ---------------------------------------------------------------------------
__global__ void __launch_bounds__(128) flash_wmma_kernel(
    const float* __restrict__ x, const float* __restrict__ gate_w)
{
    __shared__ __align__(16) unsigned char smraw[39936];
    float  (*Ksm)[132] = (float  (*)[132])(smraw);
    __half (*Vsm)[136] = (__half (*)[136])(smraw + 16896);

    const int h = blockIdx.y;
    const int qb = (int)gridDim.x - 1 - (int)blockIdx.x;   // heavy tiles first
    const int tid = threadIdx.x, warp = tid >> 5, lane = tid & 31;
    const int qbase = qb * 64;
    const int wrow0 = qbase + warp * 16;
    const int myrow = lane >> 1;
    const int myhalf = lane & 1;
    const int grow = wrow0 + myrow;

    float  (*Ssm_w)[36] = (float  (*)[36])(smraw + 25600 + warp * 2304);
    __half (*Psm_w)[40] = (__half (*)[40])(smraw + 34816 + warp * 1280);

    const float* Qh = g_q + (size_t)h * TT * HD;
    const float* Kh = g_k + (size_t)h * TT * HD;
    const float* Vh = g_v + (size_t)h * TT * HD;

    const float QS = ATTN_SCALE * LOG2E;
    wmma::fragment<wmma::matrix_a, 16, 16, 8,
                   wmma::precision::tf32, wmma::row_major> qf[16];
#pragma unroll
    for (int kt = 0; kt < 16; kt++) {
        wmma::load_matrix_sync(qf[kt], Qh + (size_t)wrow0 * HD + kt * 8, HD);
#pragma unroll
        for (int e = 0; e < qf[kt].num_elements; e++) qf[kt].x[e] *= QS;
    }

    wmma::fragment<wmma::accumulator, 16, 16, 16, float> oacc[8];
#pragma unroll
    for (int nt = 0; nt < 8; nt++) wmma::fill_fragment(oacc[nt], 0.0f);
    float lrun = 0.0f;

    const int nkb = 2 * qb + 2;
    for (int kb = 0; kb < nkb; kb++) {
        const int kbase = kb * 32;
        __syncthreads();
#pragma unroll
        for (int i = 0; i < 8; i++) {
            int idx = tid + i * 128;
            int rr = idx >> 5;
            int c4 = (idx & 31) * 4;
            float4 kv4 = *(const float4*)(Kh + (size_t)(kbase + rr) * HD + c4);
            *(float4*)&Ksm[rr][c4] = kv4;
            float4 vv4 = *(const float4*)(Vh + (size_t)(kbase + rr) * HD + c4);
            *(__half2*)&Vsm[rr][c4]     = __floats2half2_rn(vv4.x, vv4.y);
            *(__half2*)&Vsm[rr][c4 + 2] = __floats2half2_rn(vv4.z, vv4.w);
        }
        __syncthreads();

        const bool active = (kbase <= wrow0 + 15);   // warp-uniform
        if (active) {
            wmma::fragment<wmma::accumulator, 16, 16, 8, float> sacc[2];
            wmma::fill_fragment(sacc[0], 0.0f);
            wmma::fill_fragment(sacc[1], 0.0f);
#pragma unroll
            for (int kt = 0; kt < 16; kt++) {
                wmma::fragment<wmma::matrix_a, 16, 16, 8,
                               wmma::precision::tf32, wmma::row_major> ah, al;
#pragma unroll
                for (int e = 0; e < ah.num_elements; e++) {
                    float v = qf[kt].x[e];
                    float hi = tf32_hi(v);
                    ah.x[e] = hi;
                    al.x[e] = tf32_hi(v - hi);
                }
#pragma unroll
                for (int nt = 0; nt < 2; nt++) {
                    wmma::fragment<wmma::matrix_b, 16, 16, 8,
                                   wmma::precision::tf32, wmma::col_major> bh, bl;
                    wmma::load_matrix_sync(bh, &Ksm[nt * 16][kt * 8], 132);
#pragma unroll
                    for (int e = 0; e < bh.num_elements; e++) {
                        float v = bh.x[e];
                        float hi = tf32_hi(v);
                        bh.x[e] = hi;
                        bl.x[e] = tf32_hi(v - hi);
                    }
                    wmma::mma_sync(sacc[nt], ah, bh, sacc[nt]);
                    wmma::mma_sync(sacc[nt], al, bh, sacc[nt]);
                    wmma::mma_sync(sacc[nt], ah, bl, sacc[nt]);
                }
            }
            wmma::store_matrix_sync(&Ssm_w[0][0],  sacc[0], 36, wmma::mem_row_major);
            wmma::store_matrix_sync(&Ssm_w[0][16], sacc[1], 36, wmma::mem_row_major);
        }
        __syncwarp();
        if (active) {
            float lsum = 0.0f;
#pragma unroll
            for (int j = 0; j < 16; j++) {
                int col = myhalf * 16 + j;
                int gcol = kbase + col;
                float sv = Ssm_w[myrow][col];
                float p = (gcol <= grow) ? exp2f(sv - SOFT_SHIFT) : 0.0f;
                lsum += p;
                Psm_w[myrow][col] = __float2half(p);
            }
            lsum += __shfl_xor_sync(0xffffffffu, lsum, 1);
            lrun += lsum;
        }
        __syncwarp();
        if (active) {
#pragma unroll
            for (int ks = 0; ks < 2; ks++) {
                wmma::fragment<wmma::matrix_a, 16, 16, 16,
                               __half, wmma::row_major> pfrag;
                wmma::load_matrix_sync(pfrag, &Psm_w[0][ks * 16], 40);
#pragma unroll
                for (int nt = 0; nt < 8; nt++) {
                    wmma::fragment<wmma::matrix_b, 16, 16, 16,
                                   __half, wmma::row_major> vfrag;
                    wmma::load_matrix_sync(vfrag, &Vsm[ks * 16][nt * 16], 136);
                    wmma::mma_sync(oacc[nt], pfrag, vfrag, oacc[nt]);
                }
            }
        }
    }

    __syncthreads();
    float (*Osm_w)[132] = (float (*)[132])(smraw + warp * 8448);
#pragma unroll
    for (int nt = 0; nt < 8; nt++)
        wmma::store_matrix_sync(&Osm_w[0][nt * 16], oacc[nt], 132,
                                wmma::mem_row_major);
    __syncwarp();

    float gd = 0.0f;
#pragma unroll
    for (int i = 0; i < GATE_IN; i++)
        gd += x[(size_t)grow * DD + i] * gate_w[h * GATE_IN + i];
    float gate = 1.0f / (1.0f + expf(-gd));
    float scale = gate / lrun;

    const int c0 = myhalf * 64;
    float* yrow = g_y + (size_t)grow * DD + h * HD;
#pragma unroll
    for (int j = 0; j < 16; j++) {
        float4 ov = *(float4*)&Osm_w[myrow][c0 + j * 4];
        ov.x *= scale; ov.y *= scale; ov.z *= scale; ov.w *= scale;
        *(float4*)(yrow + c0 + j * 4) = ov;
    }
}

// ---------------------------------------------------------------------------
extern "C" void kernel_launch(void* const* d_in, const int* in_sizes, int n_in,
                              void* d_out, int out_size)
{
    const float* x      = (const float*)d_in[0];  // (1,2048,1024)
    const float* qkvo_w = (const float*)d_in[1];  // (4,1024,1024)
    const float* gate_w = (const float*)d_in[2];  // (8,12)
    const float* ve     = (const float*)d_in[3];  // (1,2048,8,128)
    const float* lam    = (const float*)d_in[4];  // (2,)
    const float* cosb   = (const float*)d_in[5];  // (2048,64)
    const float* sinb   = (const float*)d_in[6];  // (2048,64)
    float* out = (float*)d_out;                   // (1,2048,1024)

    // 1) QKV projection -> g_qkv
    {
        dim3 grid(3072 / 128, 2048 / 128);
        gemm_f16x3_kernel<0><<<grid, 256>>>(x, qkvo_w, nullptr, TT, 3 * DD, DD);
    }
    // 2) rms_norm + rotary + value mix
    postproc_kernel<<<TT * NH, 128>>>(ve, lam, cosb, sinb);
    // 3) causal flash attention + gate -> g_y
    {
        dim3 grid(TT / 64, NH);
        flash_wmma_kernel<<<grid, 128>>>(x, gate_w);
    }
    // 4) output projection
    {
        dim3 grid(1024 / 128, 2048 / 128);
        gemm_f16x3_kernel<1><<<grid, 256>>>(nullptr, qkvo_w + (size_t)3 * DD * DD,
                                            out, TT, DD, DD);
    }
}

// round 9
// speedup vs baseline: 2.7645x; 1.2698x over previous
#include <cuda_runtime.h>
#include <cuda_fp16.h>
#include <mma.h>
#include <math.h>

using namespace nvcuda;

#define TT 2048
#define DD 1024
#define NH 8
#define HD 128
#define GATE_IN 12

#define ATTN_SCALE 0.12f
#define RMS_EPS 1e-6f
#define LOG2E 1.4426950408889634f
#define SOFT_SHIFT 8.0f

static __device__ float  g_qkv[(size_t)TT * 3 * DD];  // [t][3*D]
static __device__ __half g_qh[(size_t)NH * TT * HD];  // scaled q hi
static __device__ __half g_ql[(size_t)NH * TT * HD];  // scaled q lo
static __device__ __half g_kh[(size_t)NH * TT * HD];  // k hi
static __device__ __half g_kl[(size_t)NH * TT * HD];  // k lo
static __device__ __half g_vh[(size_t)NH * TT * HD];  // v half
static __device__ float  g_y[(size_t)TT * DD];        // [t][h*HD+hd]

// ---------------------------------------------------------------------------
// Split-f16 GEMM via wmma: C[m][n] = sum_k A[m][k] * W[n][k]
// Block 64x128, BK=16, 256 threads = 8 warps (2x4); warp tile 32x32.
// x = h + l (f16 each, 22-bit effective); D = ah*bh + al*bh + ah*bl.
// MODE 0: A = external (x), C = g_qkv.  MODE 1: A = g_y, C = external.
// ---------------------------------------------------------------------------
template <int MODE>
__global__ void __launch_bounds__(256) gemm_f16x3_kernel(
    const float* __restrict__ Aext, const float* __restrict__ Bw,
    float* __restrict__ Cext, int M, int N, int K)
{
    const float* __restrict__ A = (MODE == 0) ? Aext : (const float*)g_y;
    float* __restrict__ C       = (MODE == 0) ? (float*)g_qkv : Cext;

    __shared__ __half Ah[64][24];    // [m][k] hi
    __shared__ __half Al[64][24];    // [m][k] lo
    __shared__ __half Bh[128][24];   // [n][k] hi
    __shared__ __half Bl[128][24];   // [n][k] lo

    const int tid = threadIdx.x;
    const int warp = tid >> 5;
    const int wm = warp >> 2;       // 0..1
    const int wn = warp & 3;        // 0..3
    const int bm = blockIdx.y * 64, bn = blockIdx.x * 128;
    const int lrow = tid >> 2;          // 0..63
    const int lc4 = (tid & 3) * 4;      // 0,4,8,12

    wmma::fragment<wmma::accumulator, 16, 16, 16, float> acc[2][2];
#pragma unroll
    for (int mt = 0; mt < 2; mt++)
#pragma unroll
        for (int nt = 0; nt < 2; nt++)
            wmma::fill_fragment(acc[mt][nt], 0.0f);

    for (int kt = 0; kt < K; kt += 16) {
        __syncthreads();
        // A tile: 64 rows, one float4 per thread
        {
            float4 av = *(const float4*)(A + (size_t)(bm + lrow) * K + kt + lc4);
            float va[4];
            va[0] = av.x; va[1] = av.y; va[2] = av.z; va[3] = av.w;
#pragma unroll
            for (int j = 0; j < 4; j++) {
                __half hv = __float2half_rn(va[j]);
                Ah[lrow][lc4 + j] = hv;
                Al[lrow][lc4 + j] = __float2half_rn(va[j] - __half2float(hv));
            }
        }
        // B tile: 128 rows, two float4 per thread
#pragma unroll
        for (int p = 0; p < 2; p++) {
            const int rr = lrow + p * 64;
            float4 bv = *(const float4*)(Bw + (size_t)(bn + rr) * K + kt + lc4);
            float vb[4];
            vb[0] = bv.x; vb[1] = bv.y; vb[2] = bv.z; vb[3] = bv.w;
#pragma unroll
            for (int j = 0; j < 4; j++) {
                __half hv = __float2half_rn(vb[j]);
                Bh[rr][lc4 + j] = hv;
                Bl[rr][lc4 + j] = __float2half_rn(vb[j] - __half2float(hv));
            }
        }
        __syncthreads();

        wmma::fragment<wmma::matrix_a, 16, 16, 16, __half,
                       wmma::row_major> fah[2], fal[2];
#pragma unroll
        for (int mt = 0; mt < 2; mt++) {
            wmma::load_matrix_sync(fah[mt], &Ah[wm * 32 + mt * 16][0], 24);
            wmma::load_matrix_sync(fal[mt], &Al[wm * 32 + mt * 16][0], 24);
        }
#pragma unroll
        for (int nt = 0; nt < 2; nt++) {
            wmma::fragment<wmma::matrix_b, 16, 16, 16, __half,
                           wmma::col_major> fbh, fbl;
            wmma::load_matrix_sync(fbh, &Bh[wn * 32 + nt * 16][0], 24);
            wmma::load_matrix_sync(fbl, &Bl[wn * 32 + nt * 16][0], 24);
#pragma unroll
            for (int mt = 0; mt < 2; mt++) {
                wmma::mma_sync(acc[mt][nt], fah[mt], fbh, acc[mt][nt]);
                wmma::mma_sync(acc[mt][nt], fal[mt], fbh, acc[mt][nt]);
                wmma::mma_sync(acc[mt][nt], fah[mt], fbl, acc[mt][nt]);
            }
        }
    }

#pragma unroll
    for (int mt = 0; mt < 2; mt++)
#pragma unroll
        for (int nt = 0; nt < 2; nt++) {
            float* cp = C + (size_t)(bm + wm * 32 + mt * 16) * N
                          + bn + wn * 32 + nt * 16;
            wmma::store_matrix_sync(cp, acc[mt][nt], N, wmma::mem_row_major);
        }
}

// ---------------------------------------------------------------------------
// Postprocess: per (t,h): rms_norm + rotary on q,k; v = l0*v + l1*ve.
// Emits pre-scaled f16 hi/lo splits for q (scale*log2e folded) and k,
// and half-precision v.
// ---------------------------------------------------------------------------
__global__ void postproc_kernel(const float* __restrict__ ve,
                                const float* __restrict__ lam,
                                const float* __restrict__ cosb,
                                const float* __restrict__ sinb)
{
    const int t = blockIdx.x >> 3;
    const int h = blockIdx.x & 7;
    const int hd = threadIdx.x;

    const float* rowp = g_qkv + (size_t)t * (3 * DD) + h * HD;
    float qv = rowp[hd];
    float kv = rowp[DD + hd];
    float vv = rowp[2 * DD + hd];

    float sq = qv * qv, sk = kv * kv;
#pragma unroll
    for (int o = 16; o; o >>= 1) {
        sq += __shfl_xor_sync(0xffffffffu, sq, o);
        sk += __shfl_xor_sync(0xffffffffu, sk, o);
    }
    __shared__ float red[2][4];
    int w = hd >> 5, lane = hd & 31;
    if (lane == 0) { red[0][w] = sq; red[1][w] = sk; }
    __syncthreads();
    sq = red[0][0] + red[0][1] + red[0][2] + red[0][3];
    sk = red[1][0] + red[1][1] + red[1][2] + red[1][3];
    float qr = rsqrtf(sq * (1.0f / HD) + RMS_EPS);
    float kr = rsqrtf(sk * (1.0f / HD) + RMS_EPS);

    __shared__ float qn[HD], kn[HD];
    qn[hd] = qv * qr;
    kn[hd] = kv * kr;
    __syncthreads();

    float qo, ko;
    if (hd < 64) {
        float cc = cosb[t * 64 + hd];
        float ss = sinb[t * 64 + hd];
        qo = qn[hd] * cc + qn[hd + 64] * ss;
        ko = kn[hd] * cc + kn[hd + 64] * ss;
    } else {
        int j = hd - 64;
        float cc = cosb[t * 64 + j];
        float ss = sinb[t * 64 + j];
        qo = -qn[j] * ss + qn[hd] * cc;
        ko = -kn[j] * ss + kn[hd] * cc;
    }
    const float lm0 = __ldg(lam);
    const float lm1 = __ldg(lam + 1);
    size_t oidx = ((size_t)h * TT + t) * HD + hd;

    float qs = qo * (ATTN_SCALE * LOG2E);
    __half qhh = __float2half_rn(qs);
    g_qh[oidx] = qhh;
    g_ql[oidx] = __float2half_rn(qs - __half2float(qhh));
    __half khh = __float2half_rn(ko);
    g_kh[oidx] = khh;
    g_kl[oidx] = __float2half_rn(ko - __half2float(khh));
    float vo = lm0 * vv + lm1 * ve[((size_t)t * NH + h) * HD + hd];
    g_vh[oidx] = __float2half_rn(vo);
}

// ---------------------------------------------------------------------------
// Flash attention, all-f16 wmma. Grid (32, 8), 128 threads = 4 warps.
// Warp owns 16 q rows; key tiles of 32.
// QK: f16 3-term split (qh persistent in regs, ql from global/L1,
// kh/kl staged in smem). Softmax: fixed shift exp2(s - 8); O never rescaled.
// PV: half wmma. Gate fused in epilogue.
// ---------------------------------------------------------------------------
__global__ void __launch_bounds__(128) flash_wmma_kernel(
    const float* __restrict__ x, const float* __restrict__ gate_w)
{
    // smem (bytes):
    //   0     : Khs 32x136 half = 8704
    //   8704  : Kls 32x136 half = 8704
    //   17408 : Vsm 32x136 half = 8704
    //   26112 : Ssm per warp 16x36 f32 (2304 ea) = 9216
    //   35328 : Psm per warp 16x40 half (1280 ea) = 5120
    //   total 40448.  Epilogue reuses [0..33792) as per-warp 16x132 f32.
    __shared__ __align__(16) unsigned char smraw[40448];
    __half (*Khs)[136] = (__half (*)[136])(smraw);
    __half (*Kls)[136] = (__half (*)[136])(smraw + 8704);
    __half (*Vsm)[136] = (__half (*)[136])(smraw + 17408);

    const int h = blockIdx.y;
    const int qb = (int)gridDim.x - 1 - (int)blockIdx.x;   // heavy tiles first
    const int tid = threadIdx.x, warp = tid >> 5, lane = tid & 31;
    const int qbase = qb * 64;
    const int wrow0 = qbase + warp * 16;
    const int myrow = lane >> 1;
    const int myhalf = lane & 1;
    const int grow = wrow0 + myrow;

    float  (*Ssm_w)[36] = (float  (*)[36])(smraw + 26112 + warp * 2304);
    __half (*Psm_w)[40] = (__half (*)[40])(smraw + 35328 + warp * 1280);

    const __half* Qhp = g_qh + (size_t)h * TT * HD;
    const __half* Qlp = g_ql + (size_t)h * TT * HD;
    const __half* Khp = g_kh + (size_t)h * TT * HD;
    const __half* Klp = g_kl + (size_t)h * TT * HD;
    const __half* Vp  = g_vh + (size_t)h * TT * HD;

    // persistent qh fragments (pre-scaled, pre-split)
    wmma::fragment<wmma::matrix_a, 16, 16, 16, __half, wmma::row_major> qhf[8];
#pragma unroll
    for (int kt = 0; kt < 8; kt++)
        wmma::load_matrix_sync(qhf[kt], Qhp + (size_t)wrow0 * HD + kt * 16, HD);

    wmma::fragment<wmma::accumulator, 16, 16, 16, float> oacc[8];
#pragma unroll
    for (int nt = 0; nt < 8; nt++) wmma::fill_fragment(oacc[nt], 0.0f);
    float lrun = 0.0f;

    const int nkb = 2 * qb + 2;
    for (int kb = 0; kb < nkb; kb++) {
        const int kbase = kb * 32;
        __syncthreads();
        // cooperative load: kh, kl, v tiles (32 x 128 halves each)
#pragma unroll
        for (int i = 0; i < 4; i++) {
            int idx = tid + i * 128;           // 0..511
            int rr = idx >> 4;                 // 0..31
            int c8 = (idx & 15) * 8;           // 0..120 step 8
            size_t goff = (size_t)(kbase + rr) * HD + c8;
            *(float4*)&Khs[rr][c8] = *(const float4*)(Khp + goff);
            *(float4*)&Kls[rr][c8] = *(const float4*)(Klp + goff);
            *(float4*)&Vsm[rr][c8] = *(const float4*)(Vp + goff);
        }
        __syncthreads();

        const bool active = (kbase <= wrow0 + 15);   // warp-uniform
        if (active) {
            wmma::fragment<wmma::accumulator, 16, 16, 16, float> sacc[2];
            wmma::fill_fragment(sacc[0], 0.0f);
            wmma::fill_fragment(sacc[1], 0.0f);
#pragma unroll
            for (int kt = 0; kt < 8; kt++) {
                wmma::fragment<wmma::matrix_a, 16, 16, 16, __half,
                               wmma::row_major> qlf;
                wmma::load_matrix_sync(qlf, Qlp + (size_t)wrow0 * HD + kt * 16, HD);
#pragma unroll
                for (int nt = 0; nt < 2; nt++) {
                    wmma::fragment<wmma::matrix_b, 16, 16, 16, __half,
                                   wmma::col_major> khf, klf;
                    wmma::load_matrix_sync(khf, &Khs[nt * 16][kt * 16], 136);
                    wmma::load_matrix_sync(klf, &Kls[nt * 16][kt * 16], 136);
                    wmma::mma_sync(sacc[nt], qhf[kt], khf, sacc[nt]);
                    wmma::mma_sync(sacc[nt], qlf,     khf, sacc[nt]);
                    wmma::mma_sync(sacc[nt], qhf[kt], klf, sacc[nt]);
                }
            }
            wmma::store_matrix_sync(&Ssm_w[0][0],  sacc[0], 36, wmma::mem_row_major);
            wmma::store_matrix_sync(&Ssm_w[0][16], sacc[1], 36, wmma::mem_row_major);
        }
        __syncwarp();
        if (active) {
            // softmax, fixed shift; causal mask; P as half
            float lsum = 0.0f;
#pragma unroll
            for (int j = 0; j < 16; j++) {
                int col = myhalf * 16 + j;
                int gcol = kbase + col;
                float sv = Ssm_w[myrow][col];
                float p = (gcol <= grow) ? exp2f(sv - SOFT_SHIFT) : 0.0f;
                lsum += p;
                Psm_w[myrow][col] = __float2half(p);
            }
            lsum += __shfl_xor_sync(0xffffffffu, lsum, 1);
            lrun += lsum;
        }
        __syncwarp();
        if (active) {
            // O += P V
#pragma unroll
            for (int ks = 0; ks < 2; ks++) {
                wmma::fragment<wmma::matrix_a, 16, 16, 16,
                               __half, wmma::row_major> pfrag;
                wmma::load_matrix_sync(pfrag, &Psm_w[0][ks * 16], 40);
#pragma unroll
                for (int nt = 0; nt < 8; nt++) {
                    wmma::fragment<wmma::matrix_b, 16, 16, 16,
                                   __half, wmma::row_major> vfrag;
                    wmma::load_matrix_sync(vfrag, &Vsm[ks * 16][nt * 16], 136);
                    wmma::mma_sync(oacc[nt], pfrag, vfrag, oacc[nt]);
                }
            }
        }
    }

    // epilogue: stage O to smem, normalize, gate, store
    __syncthreads();
    float (*Osm_w)[132] = (float (*)[132])(smraw + warp * 8448);
#pragma unroll
    for (int nt = 0; nt < 8; nt++)
        wmma::store_matrix_sync(&Osm_w[0][nt * 16], oacc[nt], 132,
                                wmma::mem_row_major);
    __syncwarp();

    float gd = 0.0f;
#pragma unroll
    for (int i = 0; i < GATE_IN; i++)
        gd += x[(size_t)grow * DD + i] * gate_w[h * GATE_IN + i];
    float gate = 1.0f / (1.0f + expf(-gd));
    float scale = gate / lrun;

    const int c0 = myhalf * 64;
    float* yrow = g_y + (size_t)grow * DD + h * HD;
#pragma unroll
    for (int j = 0; j < 16; j++) {
        float4 ov = *(float4*)&Osm_w[myrow][c0 + j * 4];
        ov.x *= scale; ov.y *= scale; ov.z *= scale; ov.w *= scale;
        *(float4*)(yrow + c0 + j * 4) = ov;
    }
}

// ---------------------------------------------------------------------------
extern "C" void kernel_launch(void* const* d_in, const int* in_sizes, int n_in,
                              void* d_out, int out_size)
{
    const float* x      = (const float*)d_in[0];  // (1,2048,1024)
    const float* qkvo_w = (const float*)d_in[1];  // (4,1024,1024)
    const float* gate_w = (const float*)d_in[2];  // (8,12)
    const float* ve     = (const float*)d_in[3];  // (1,2048,8,128)
    const float* lam    = (const float*)d_in[4];  // (2,)
    const float* cosb   = (const float*)d_in[5];  // (2048,64)
    const float* sinb   = (const float*)d_in[6];  // (2048,64)
    float* out = (float*)d_out;                   // (1,2048,1024)

    // 1) QKV projection -> g_qkv
    {
        dim3 grid(3072 / 128, 2048 / 64);
        gemm_f16x3_kernel<0><<<grid, 256>>>(x, qkvo_w, nullptr, TT, 3 * DD, DD);
    }
    // 2) rms_norm + rotary + value mix + split
    postproc_kernel<<<TT * NH, 128>>>(ve, lam, cosb, sinb);
    // 3) causal flash attention + gate -> g_y
    {
        dim3 grid(TT / 64, NH);
        flash_wmma_kernel<<<grid, 128>>>(x, gate_w);
    }
    // 4) output projection
    {
        dim3 grid(1024 / 128, 2048 / 64);
        gemm_f16x3_kernel<1><<<grid, 256>>>(nullptr, qkvo_w + (size_t)3 * DD * DD,
                                            out, TT, DD, DD);
    }
}

// round 10
// speedup vs baseline: 2.9959x; 1.0837x over previous
#include <cuda_runtime.h>
#include <cuda_fp16.h>
#include <mma.h>
#include <math.h>

using namespace nvcuda;

#define TT 2048
#define DD 1024
#define NH 8
#define HD 128
#define GATE_IN 12

#define ATTN_SCALE 0.12f
#define RMS_EPS 1e-6f
#define LOG2E 1.4426950408889634f
#define SOFT_SHIFT 8.0f

static __device__ float  g_qkv[(size_t)TT * 3 * DD];  // [t][3*D]
static __device__ __half g_wh[(size_t)4 * DD * DD];   // weight hi
static __device__ __half g_wl[(size_t)4 * DD * DD];   // weight lo
static __device__ __half g_xh[(size_t)TT * DD];       // x hi
static __device__ __half g_xl[(size_t)TT * DD];       // x lo
static __device__ __half g_yh[(size_t)TT * DD];       // y hi
static __device__ __half g_yl[(size_t)TT * DD];       // y lo
static __device__ __half g_qh[(size_t)NH * TT * HD];  // scaled q hi
static __device__ __half g_ql[(size_t)NH * TT * HD];  // scaled q lo
static __device__ __half g_kh[(size_t)NH * TT * HD];  // k hi
static __device__ __half g_kl[(size_t)NH * TT * HD];  // k lo
static __device__ __half g_vh[(size_t)NH * TT * HD];  // v half

// ---------------------------------------------------------------------------
// split f32 -> (hi, lo) f16 pair.  MODE 0: w -> g_wh/g_wl. MODE 1: x -> g_xh/g_xl.
// ---------------------------------------------------------------------------
template <int MODE>
__global__ void split_kernel(const float* __restrict__ src)
{
    __half* __restrict__ dh = (MODE == 0) ? g_wh : g_xh;
    __half* __restrict__ dl = (MODE == 0) ? g_wl : g_xl;
    int i = blockIdx.x * blockDim.x + threadIdx.x;
    float4 v = ((const float4*)src)[i];
    __half h0 = __float2half_rn(v.x), h1 = __float2half_rn(v.y);
    __half h2 = __float2half_rn(v.z), h3 = __float2half_rn(v.w);
    __half l0 = __float2half_rn(v.x - __half2float(h0));
    __half l1 = __float2half_rn(v.y - __half2float(h1));
    __half l2 = __float2half_rn(v.z - __half2float(h2));
    __half l3 = __float2half_rn(v.w - __half2float(h3));
    __half2* dh2 = (__half2*)dh;
    __half2* dl2 = (__half2*)dl;
    dh2[i * 2]     = __halves2half2(h0, h1);
    dh2[i * 2 + 1] = __halves2half2(h2, h3);
    dl2[i * 2]     = __halves2half2(l0, l1);
    dl2[i * 2 + 1] = __halves2half2(l2, l3);
}

// ---------------------------------------------------------------------------
// f16x3 GEMM on pre-split halves: C[m][n] = sum_k A[m][k]*W[n][k]
// Block 64x128, BK=32, 128 threads = 4 warps (2x2); warp tile 32x64.
// Inner loop: pure fragment loads + mma (no conversions).
// MODE 0: A = g_xh/g_xl, B = g_wh/g_wl[0:3D], C = g_qkv.
// MODE 1: A = g_yh/g_yl, B = g_wh/g_wl[3D:4D], C = out.
// ---------------------------------------------------------------------------
template <int MODE>
__global__ void __launch_bounds__(128) gemm_presplit_kernel(
    float* __restrict__ Cext, int M, int N, int K)
{
    const __half* __restrict__ Ahp = (MODE == 0) ? g_xh : g_yh;
    const __half* __restrict__ Alp = (MODE == 0) ? g_xl : g_yl;
    const __half* __restrict__ Bhp = g_wh + (MODE == 0 ? 0 : (size_t)3 * DD * DD);
    const __half* __restrict__ Blp = g_wl + (MODE == 0 ? 0 : (size_t)3 * DD * DD);
    float* __restrict__ C = (MODE == 0) ? (float*)g_qkv : Cext;

    __shared__ __half Ah[64][40];    // [m][k], BK=32 padded to 40
    __shared__ __half Al[64][40];
    __shared__ __half Bh[128][40];   // [n][k]
    __shared__ __half Bl[128][40];

    const int tid = threadIdx.x;
    const int warp = tid >> 5;
    const int wm = warp >> 1;       // 0..1
    const int wn = warp & 1;        // 0..1
    const int bm = blockIdx.y * 64, bn = blockIdx.x * 128;

    wmma::fragment<wmma::accumulator, 16, 16, 16, float> acc[2][4];
#pragma unroll
    for (int mt = 0; mt < 2; mt++)
#pragma unroll
        for (int nt = 0; nt < 4; nt++)
            wmma::fill_fragment(acc[mt][nt], 0.0f);

    for (int kt = 0; kt < K; kt += 32) {
        __syncthreads();
        // A tiles: 64 rows x 32 halves = 256 float4s; 2 per thread (x2 arrays)
#pragma unroll
        for (int i = 0; i < 2; i++) {
            int idx = tid + i * 128;
            int rr = idx >> 2;
            int c8 = (idx & 3) * 8;
            size_t go = (size_t)(bm + rr) * K + kt + c8;
            *(float4*)&Ah[rr][c8] = *(const float4*)(Ahp + go);
            *(float4*)&Al[rr][c8] = *(const float4*)(Alp + go);
        }
        // B tiles: 128 rows x 32 halves = 512 float4s; 4 per thread (x2 arrays)
#pragma unroll
        for (int i = 0; i < 4; i++) {
            int idx = tid + i * 128;
            int rr = idx >> 2;
            int c8 = (idx & 3) * 8;
            size_t go = (size_t)(bn + rr) * K + kt + c8;
            *(float4*)&Bh[rr][c8] = *(const float4*)(Bhp + go);
            *(float4*)&Bl[rr][c8] = *(const float4*)(Blp + go);
        }
        __syncthreads();

#pragma unroll
        for (int ks = 0; ks < 32; ks += 16) {
            wmma::fragment<wmma::matrix_a, 16, 16, 16, __half,
                           wmma::row_major> fah[2], fal[2];
#pragma unroll
            for (int mt = 0; mt < 2; mt++) {
                wmma::load_matrix_sync(fah[mt], &Ah[wm * 32 + mt * 16][ks], 40);
                wmma::load_matrix_sync(fal[mt], &Al[wm * 32 + mt * 16][ks], 40);
            }
#pragma unroll
            for (int nt = 0; nt < 4; nt++) {
                wmma::fragment<wmma::matrix_b, 16, 16, 16, __half,
                               wmma::col_major> fbh, fbl;
                wmma::load_matrix_sync(fbh, &Bh[wn * 64 + nt * 16][ks], 40);
                wmma::load_matrix_sync(fbl, &Bl[wn * 64 + nt * 16][ks], 40);
#pragma unroll
                for (int mt = 0; mt < 2; mt++) {
                    wmma::mma_sync(acc[mt][nt], fah[mt], fbh, acc[mt][nt]);
                    wmma::mma_sync(acc[mt][nt], fal[mt], fbh, acc[mt][nt]);
                    wmma::mma_sync(acc[mt][nt], fah[mt], fbl, acc[mt][nt]);
                }
            }
        }
    }

#pragma unroll
    for (int mt = 0; mt < 2; mt++)
#pragma unroll
        for (int nt = 0; nt < 4; nt++) {
            float* cp = C + (size_t)(bm + wm * 32 + mt * 16) * N
                          + bn + wn * 64 + nt * 16;
            wmma::store_matrix_sync(cp, acc[mt][nt], N, wmma::mem_row_major);
        }
}

// ---------------------------------------------------------------------------
// Postprocess: per (t,h): rms_norm + rotary on q,k; v = l0*v + l1*ve.
// Emits pre-scaled f16 hi/lo splits for q (scale*log2e folded) and k, v half.
// ---------------------------------------------------------------------------
__global__ void postproc_kernel(const float* __restrict__ ve,
                                const float* __restrict__ lam,
                                const float* __restrict__ cosb,
                                const float* __restrict__ sinb)
{
    const int t = blockIdx.x >> 3;
    const int h = blockIdx.x & 7;
    const int hd = threadIdx.x;

    const float* rowp = g_qkv + (size_t)t * (3 * DD) + h * HD;
    float qv = rowp[hd];
    float kv = rowp[DD + hd];
    float vv = rowp[2 * DD + hd];

    float sq = qv * qv, sk = kv * kv;
#pragma unroll
    for (int o = 16; o; o >>= 1) {
        sq += __shfl_xor_sync(0xffffffffu, sq, o);
        sk += __shfl_xor_sync(0xffffffffu, sk, o);
    }
    __shared__ float red[2][4];
    int w = hd >> 5, lane = hd & 31;
    if (lane == 0) { red[0][w] = sq; red[1][w] = sk; }
    __syncthreads();
    sq = red[0][0] + red[0][1] + red[0][2] + red[0][3];
    sk = red[1][0] + red[1][1] + red[1][2] + red[1][3];
    float qr = rsqrtf(sq * (1.0f / HD) + RMS_EPS);
    float kr = rsqrtf(sk * (1.0f / HD) + RMS_EPS);

    __shared__ float qn[HD], kn[HD];
    qn[hd] = qv * qr;
    kn[hd] = kv * kr;
    __syncthreads();

    float qo, ko;
    if (hd < 64) {
        float cc = cosb[t * 64 + hd];
        float ss = sinb[t * 64 + hd];
        qo = qn[hd] * cc + qn[hd + 64] * ss;
        ko = kn[hd] * cc + kn[hd + 64] * ss;
    } else {
        int j = hd - 64;
        float cc = cosb[t * 64 + j];
        float ss = sinb[t * 64 + j];
        qo = -qn[j] * ss + qn[hd] * cc;
        ko = -kn[j] * ss + kn[hd] * cc;
    }
    const float lm0 = __ldg(lam);
    const float lm1 = __ldg(lam + 1);
    size_t oidx = ((size_t)h * TT + t) * HD + hd;

    float qs = qo * (ATTN_SCALE * LOG2E);
    __half qhh = __float2half_rn(qs);
    g_qh[oidx] = qhh;
    g_ql[oidx] = __float2half_rn(qs - __half2float(qhh));
    __half khh = __float2half_rn(ko);
    g_kh[oidx] = khh;
    g_kl[oidx] = __float2half_rn(ko - __half2float(khh));
    float vo = lm0 * vv + lm1 * ve[((size_t)t * NH + h) * HD + hd];
    g_vh[oidx] = __float2half_rn(vo);
}

// ---------------------------------------------------------------------------
// Flash attention, all-f16 wmma. Grid (32, 8), 128 threads = 4 warps.
// Identical mainloop to round-9 (measured good); epilogue writes y as
// (hi, lo) f16 pair for the pre-split O-projection.
// ---------------------------------------------------------------------------
__global__ void __launch_bounds__(128) flash_wmma_kernel(
    const float* __restrict__ x, const float* __restrict__ gate_w)
{
    __shared__ __align__(16) unsigned char smraw[40448];
    __half (*Khs)[136] = (__half (*)[136])(smraw);
    __half (*Kls)[136] = (__half (*)[136])(smraw + 8704);
    __half (*Vsm)[136] = (__half (*)[136])(smraw + 17408);

    const int h = blockIdx.y;
    const int qb = (int)gridDim.x - 1 - (int)blockIdx.x;   // heavy tiles first
    const int tid = threadIdx.x, warp = tid >> 5, lane = tid & 31;
    const int qbase = qb * 64;
    const int wrow0 = qbase + warp * 16;
    const int myrow = lane >> 1;
    const int myhalf = lane & 1;
    const int grow = wrow0 + myrow;

    float  (*Ssm_w)[36] = (float  (*)[36])(smraw + 26112 + warp * 2304);
    __half (*Psm_w)[40] = (__half (*)[40])(smraw + 35328 + warp * 1280);

    const __half* Qhp = g_qh + (size_t)h * TT * HD;
    const __half* Qlp = g_ql + (size_t)h * TT * HD;
    const __half* Khp = g_kh + (size_t)h * TT * HD;
    const __half* Klp = g_kl + (size_t)h * TT * HD;
    const __half* Vp  = g_vh + (size_t)h * TT * HD;

    wmma::fragment<wmma::matrix_a, 16, 16, 16, __half, wmma::row_major> qhf[8];
#pragma unroll
    for (int kt = 0; kt < 8; kt++)
        wmma::load_matrix_sync(qhf[kt], Qhp + (size_t)wrow0 * HD + kt * 16, HD);

    wmma::fragment<wmma::accumulator, 16, 16, 16, float> oacc[8];
#pragma unroll
    for (int nt = 0; nt < 8; nt++) wmma::fill_fragment(oacc[nt], 0.0f);
    float lrun = 0.0f;

    const int nkb = 2 * qb + 2;
    for (int kb = 0; kb < nkb; kb++) {
        const int kbase = kb * 32;
        __syncthreads();
#pragma unroll
        for (int i = 0; i < 4; i++) {
            int idx = tid + i * 128;
            int rr = idx >> 4;
            int c8 = (idx & 15) * 8;
            size_t goff = (size_t)(kbase + rr) * HD + c8;
            *(float4*)&Khs[rr][c8] = *(const float4*)(Khp + goff);
            *(float4*)&Kls[rr][c8] = *(const float4*)(Klp + goff);
            *(float4*)&Vsm[rr][c8] = *(const float4*)(Vp + goff);
        }
        __syncthreads();

        const bool active = (kbase <= wrow0 + 15);   // warp-uniform
        if (active) {
            wmma::fragment<wmma::accumulator, 16, 16, 16, float> sacc[2];
            wmma::fill_fragment(sacc[0], 0.0f);
            wmma::fill_fragment(sacc[1], 0.0f);
#pragma unroll
            for (int kt = 0; kt < 8; kt++) {
                wmma::fragment<wmma::matrix_a, 16, 16, 16, __half,
                               wmma::row_major> qlf;
                wmma::load_matrix_sync(qlf, Qlp + (size_t)wrow0 * HD + kt * 16, HD);
#pragma unroll
                for (int nt = 0; nt < 2; nt++) {
                    wmma::fragment<wmma::matrix_b, 16, 16, 16, __half,
                                   wmma::col_major> khf, klf;
                    wmma::load_matrix_sync(khf, &Khs[nt * 16][kt * 16], 136);
                    wmma::load_matrix_sync(klf, &Kls[nt * 16][kt * 16], 136);
                    wmma::mma_sync(sacc[nt], qhf[kt], khf, sacc[nt]);
                    wmma::mma_sync(sacc[nt], qlf,     khf, sacc[nt]);
                    wmma::mma_sync(sacc[nt], qhf[kt], klf, sacc[nt]);
                }
            }
            wmma::store_matrix_sync(&Ssm_w[0][0],  sacc[0], 36, wmma::mem_row_major);
            wmma::store_matrix_sync(&Ssm_w[0][16], sacc[1], 36, wmma::mem_row_major);
        }
        __syncwarp();
        if (active) {
            float lsum = 0.0f;
#pragma unroll
            for (int j = 0; j < 16; j++) {
                int col = myhalf * 16 + j;
                int gcol = kbase + col;
                float sv = Ssm_w[myrow][col];
                float p = (gcol <= grow) ? exp2f(sv - SOFT_SHIFT) : 0.0f;
                lsum += p;
                Psm_w[myrow][col] = __float2half(p);
            }
            lsum += __shfl_xor_sync(0xffffffffu, lsum, 1);
            lrun += lsum;
        }
        __syncwarp();
        if (active) {
#pragma unroll
            for (int ks = 0; ks < 2; ks++) {
                wmma::fragment<wmma::matrix_a, 16, 16, 16,
                               __half, wmma::row_major> pfrag;
                wmma::load_matrix_sync(pfrag, &Psm_w[0][ks * 16], 40);
#pragma unroll
                for (int nt = 0; nt < 8; nt++) {
                    wmma::fragment<wmma::matrix_b, 16, 16, 16,
                                   __half, wmma::row_major> vfrag;
                    wmma::load_matrix_sync(vfrag, &Vsm[ks * 16][nt * 16], 136);
                    wmma::mma_sync(oacc[nt], pfrag, vfrag, oacc[nt]);
                }
            }
        }
    }

    // epilogue: stage O to smem, normalize, gate, emit (hi, lo) halves
    __syncthreads();
    float (*Osm_w)[132] = (float (*)[132])(smraw + warp * 8448);
#pragma unroll
    for (int nt = 0; nt < 8; nt++)
        wmma::store_matrix_sync(&Osm_w[0][nt * 16], oacc[nt], 132,
                                wmma::mem_row_major);
    __syncwarp();

    float gd = 0.0f;
#pragma unroll
    for (int i = 0; i < GATE_IN; i++)
        gd += x[(size_t)grow * DD + i] * gate_w[h * GATE_IN + i];
    float gate = 1.0f / (1.0f + expf(-gd));
    float scale = gate / lrun;

    const int c0 = myhalf * 64;
    __half* yh = g_yh + (size_t)grow * DD + h * HD;
    __half* yl = g_yl + (size_t)grow * DD + h * HD;
#pragma unroll
    for (int j = 0; j < 16; j++) {
        float4 ov = *(float4*)&Osm_w[myrow][c0 + j * 4];
        float v0 = ov.x * scale, v1 = ov.y * scale;
        float v2 = ov.z * scale, v3 = ov.w * scale;
        __half h0 = __float2half_rn(v0), h1 = __float2half_rn(v1);
        __half h2 = __float2half_rn(v2), h3 = __float2half_rn(v3);
        __half2* yh2 = (__half2*)(yh + c0 + j * 4);
        yh2[0] = __halves2half2(h0, h1);
        yh2[1] = __halves2half2(h2, h3);
        __half2* yl2 = (__half2*)(yl + c0 + j * 4);
        yl2[0] = __halves2half2(__float2half_rn(v0 - __half2float(h0)),
                                __float2half_rn(v1 - __half2float(h1)));
        yl2[1] = __halves2half2(__float2half_rn(v2 - __half2float(h2)),
                                __float2half_rn(v3 - __half2float(h3)));
    }
}

// ---------------------------------------------------------------------------
extern "C" void kernel_launch(void* const* d_in, const int* in_sizes, int n_in,
                              void* d_out, int out_size)
{
    const float* x      = (const float*)d_in[0];  // (1,2048,1024)
    const float* qkvo_w = (const float*)d_in[1];  // (4,1024,1024)
    const float* gate_w = (const float*)d_in[2];  // (8,12)
    const float* ve     = (const float*)d_in[3];  // (1,2048,8,128)
    const float* lam    = (const float*)d_in[4];  // (2,)
    const float* cosb   = (const float*)d_in[5];  // (2048,64)
    const float* sinb   = (const float*)d_in[6];  // (2048,64)
    float* out = (float*)d_out;                   // (1,2048,1024)

    // 0) pre-split weights and x into f16 (hi, lo)
    split_kernel<0><<<(4 * DD * DD / 4) / 256, 256>>>(qkvo_w);
    split_kernel<1><<<(TT * DD / 4) / 256, 256>>>(x);

    // 1) QKV projection -> g_qkv
    {
        dim3 grid(3072 / 128, 2048 / 64);
        gemm_presplit_kernel<0><<<grid, 128>>>(nullptr, TT, 3 * DD, DD);
    }
    // 2) rms_norm + rotary + value mix + split
    postproc_kernel<<<TT * NH, 128>>>(ve, lam, cosb, sinb);
    // 3) causal flash attention + gate -> g_yh/g_yl
    {
        dim3 grid(TT / 64, NH);
        flash_wmma_kernel<<<grid, 128>>>(x, gate_w);
    }
    // 4) output projection
    {
        dim3 grid(1024 / 128, 2048 / 64);
        gemm_presplit_kernel<1><<<grid, 128>>>(out, TT, DD, DD);
    }
}